// round 5
// baseline (speedup 1.0000x reference)
#include <cuda_runtime.h>
#include <stdint.h>

// StridedSlice: out[n,c,h,w] = x[n,c,2h,2w]
//   in : (8,128,512,512) f32   in row = 128 float4, plane = 65536 float4
//   out: (8,128,256,256) f32   out row = 64 float4, 262144 rows total
//
// Persistent single-wave kernel: grid = 148 SMs * 8 blocks = 1184 blocks of
// 256 threads (one full residency wave, no wave transitions). Each warp
// grid-strides over 131072 two-row work units. Per unit: thread t loads its
// aligned 32 B input sector with one 256-bit load (lane stride 32 B -> each
// LDG.256 warp instruction covers a fully-consumed 1 KB span) and writes
// fully-coalesced STG.128.

#define TOTAL_UNITS 131072u   // 262144 output rows / 2 rows per unit

__device__ __forceinline__ void ldg256_cs(const float4* __restrict__ p,
                                          float4& v0, float4& v1)
{
    asm volatile("ld.global.cs.v8.f32 {%0,%1,%2,%3,%4,%5,%6,%7}, [%8];"
                 : "=f"(v0.x), "=f"(v0.y), "=f"(v0.z), "=f"(v0.w),
                   "=f"(v1.x), "=f"(v1.y), "=f"(v1.z), "=f"(v1.w)
                 : "l"(p));
}

__global__ __launch_bounds__(256) void strided_slice_kernel(
    const float4* __restrict__ in, float4* __restrict__ out)
{
    const unsigned warpStride = gridDim.x << 3;              // warps in grid
    unsigned wg = (blockIdx.x * 256u + threadIdx.x) >> 5;    // global warp id
    const unsigned t  = threadIdx.x & 31u;
    const unsigned t2 = t << 1;

    for (; wg < TOTAL_UNITS; wg += warpStride) {
        unsigned r0 = wg << 1;          // first of 2 output rows
        unsigned h  = r0 & 255u;        // even; both rows in one plane
        unsigned nc = r0 >> 8;

        const float4* __restrict__ ib =
            in + ((size_t)nc << 16) + ((size_t)h << 8);
        float4* __restrict__ ob = out + ((size_t)r0 << 6);

        float4 a0, a1, a2, a3, b0, b1, b2, b3;
        ldg256_cs(ib + t2,       a0, a1);   // row 2h,   out cols 0..31
        ldg256_cs(ib + t2 + 64,  a2, a3);   // row 2h,   out cols 32..63
        ldg256_cs(ib + t2 + 256, b0, b1);   // row 2h+2, out cols 0..31
        ldg256_cs(ib + t2 + 320, b2, b3);   // row 2h+2, out cols 32..63

        __stcs(ob + t,      make_float4(a0.x, a0.z, a1.x, a1.z));
        __stcs(ob + 32 + t, make_float4(a2.x, a2.z, a3.x, a3.z));
        __stcs(ob + 64 + t, make_float4(b0.x, b0.z, b1.x, b1.z));
        __stcs(ob + 96 + t, make_float4(b2.x, b2.z, b3.x, b3.z));
    }
}

extern "C" void kernel_launch(void* const* d_in, const int* in_sizes, int n_in,
                              void* d_out, int out_size)
{
    (void)in_sizes; (void)n_in; (void)out_size;
    const float4* in  = (const float4*)d_in[0];
    float4*       out = (float4*)d_out;

    // 148 SMs * 8 resident blocks = 1184 blocks -> exactly one wave
    strided_slice_kernel<<<1184, 256>>>(in, out);
}

// round 6
// speedup vs baseline: 1.0781x; 1.0781x over previous
#include <cuda_runtime.h>
#include <stdint.h>

// StridedSlice: out[n,c,h,w] = x[n,c,2h,2w]
//   in : (8,128,512,512) f32   in row = 128 float4, plane = 65536 float4
//   out: (8,128,256,256) f32   out row = 64 float4, 262144 rows total
//
// Flat launch (best measured shape). One warp -> 2 consecutive output rows
// (128 float4 = 2 KB) from 2 even input rows (4 KB). Thread t writes out
// float4 {t,32+t,64+t,96+t} (fully coalesced STG.128). Each output float4
// consumes one aligned 32 B input sector via a single 256-bit load (lane
// stride 32 B -> each LDG.256 warp instruction covers a fully-consumed
// contiguous 1 KB span). Default cache policy on both paths (measured best
// DRAM efficiency vs .cs streaming hints).

__device__ __forceinline__ void ldg256(const float4* __restrict__ p,
                                       float4& v0, float4& v1)
{
    asm volatile("ld.global.v8.f32 {%0,%1,%2,%3,%4,%5,%6,%7}, [%8];"
                 : "=f"(v0.x), "=f"(v0.y), "=f"(v0.z), "=f"(v0.w),
                   "=f"(v1.x), "=f"(v1.y), "=f"(v1.z), "=f"(v1.w)
                 : "l"(p));
}

__global__ __launch_bounds__(256) void strided_slice_kernel(
    const float4* __restrict__ in, float4* __restrict__ out)
{
    unsigned wg = (blockIdx.x * 256u + threadIdx.x) >> 5;  // global warp id
    unsigned t  = threadIdx.x & 31u;

    unsigned r0 = wg << 1;          // first of 2 output rows for this warp
    unsigned h  = r0 & 255u;        // even; both rows stay in one plane
    unsigned nc = r0 >> 8;

    const float4* __restrict__ ib = in + ((size_t)nc << 16) + ((size_t)h << 8);
    float4* __restrict__ ob = out + ((size_t)r0 << 6);

    unsigned t2 = t << 1;

    // 4 front-batched 256-bit loads (each lane = one aligned 32 B sector)
    float4 a0, a1, a2, a3, b0, b1, b2, b3;
    ldg256(ib + t2,       a0, a1);   // row 2h,   out cols 0..31
    ldg256(ib + t2 + 64,  a2, a3);   // row 2h,   out cols 32..63
    ldg256(ib + t2 + 256, b0, b1);   // row 2h+2, out cols 0..31
    ldg256(ib + t2 + 320, b2, b3);   // row 2h+2, out cols 32..63

    ob[t]      = make_float4(a0.x, a0.z, a1.x, a1.z);
    ob[32 + t] = make_float4(a2.x, a2.z, a3.x, a3.z);
    ob[64 + t] = make_float4(b0.x, b0.z, b1.x, b1.z);
    ob[96 + t] = make_float4(b2.x, b2.z, b3.x, b3.z);
}

extern "C" void kernel_launch(void* const* d_in, const int* in_sizes, int n_in,
                              void* d_out, int out_size)
{
    (void)in_sizes; (void)n_in; (void)out_size;
    const float4* in  = (const float4*)d_in[0];
    float4*       out = (float4*)d_out;

    // 262144 output rows / 2 rows per warp = 131072 warps = 16384 blocks of 256
    strided_slice_kernel<<<16384, 256>>>(in, out);
}

// round 7
// speedup vs baseline: 1.0916x; 1.0125x over previous
#include <cuda_runtime.h>
#include <stdint.h>

// StridedSlice: out[n,c,h,w] = x[n,c,2h,2w]
//   in : (8,128,512,512) f32   in row = 128 float4, plane = 65536 float4
//   out: (8,128,256,256) f32   out row = 64 float4, 262144 rows total
//
// Symmetric 256-bit variant. One warp -> 2 consecutive output rows.
// Per row, lane t owns out float4 [2t, 2t+1] (one 256-bit store = 32 B,
// warp instruction covers the full 1 KB row contiguously) sourced from
// in float4 [4t..4t+3] via two 256-bit loads at 64 B lane stride (the
// instruction pair fully covers the 2 KB input span).

__device__ __forceinline__ void ldg256(const float4* __restrict__ p,
                                       float4& v0, float4& v1)
{
    asm volatile("ld.global.v8.f32 {%0,%1,%2,%3,%4,%5,%6,%7}, [%8];"
                 : "=f"(v0.x), "=f"(v0.y), "=f"(v0.z), "=f"(v0.w),
                   "=f"(v1.x), "=f"(v1.y), "=f"(v1.z), "=f"(v1.w)
                 : "l"(p));
}

__device__ __forceinline__ void stg256(float4* __restrict__ p,
                                       float a, float b, float c, float d,
                                       float e, float f, float g, float h)
{
    asm volatile("st.global.v8.f32 [%0], {%1,%2,%3,%4,%5,%6,%7,%8};"
                 :: "l"(p), "f"(a), "f"(b), "f"(c), "f"(d),
                    "f"(e), "f"(f), "f"(g), "f"(h)
                 : "memory");
}

__global__ __launch_bounds__(256) void strided_slice_kernel(
    const float4* __restrict__ in, float4* __restrict__ out)
{
    unsigned wg = (blockIdx.x * 256u + threadIdx.x) >> 5;  // global warp id
    unsigned t  = threadIdx.x & 31u;

    unsigned r0 = wg << 1;          // first of 2 output rows for this warp
    unsigned h  = r0 & 255u;        // even; both rows stay in one plane
    unsigned nc = r0 >> 8;

    const float4* __restrict__ ib = in + ((size_t)nc << 16) + ((size_t)h << 8);
    float4* __restrict__ ob = out + ((size_t)r0 << 6);

    unsigned t4 = t << 2;

    // 4 front-batched 256-bit loads (64 B lane stride; pairs fully cover span)
    float4 a0, a1, a2, a3, b0, b1, b2, b3;
    ldg256(ib + t4,       a0, a1);   // row 2h,   in float4 4t..4t+1
    ldg256(ib + t4 + 2,   a2, a3);   // row 2h,   in float4 4t+2..4t+3
    ldg256(ib + t4 + 256, b0, b1);   // row 2h+2
    ldg256(ib + t4 + 258, b2, b3);

    // 2 fully-coalesced 256-bit stores (lane t -> out float4 2t..2t+1)
    stg256(ob + (t << 1),
           a0.x, a0.z, a1.x, a1.z, a2.x, a2.z, a3.x, a3.z);
    stg256(ob + 64 + (t << 1),
           b0.x, b0.z, b1.x, b1.z, b2.x, b2.z, b3.x, b3.z);
}

extern "C" void kernel_launch(void* const* d_in, const int* in_sizes, int n_in,
                              void* d_out, int out_size)
{
    (void)in_sizes; (void)n_in; (void)out_size;
    const float4* in  = (const float4*)d_in[0];
    float4*       out = (float4*)d_out;

    // 262144 output rows / 2 rows per warp = 131072 warps = 16384 blocks of 256
    strided_slice_kernel<<<16384, 256>>>(in, out);
}